// round 7
// baseline (speedup 1.0000x reference)
#include <cuda_runtime.h>
#include <cuda_fp16.h>
#include <cstdint>

// ============================ problem constants ============================
#define SS 2048
#define DD 4096
#define VV 32000
#define MROWS 4094          // B*(S-1)
#define MPAD  4096          // padded GEMM M

// scratch (device globals — allocation-free rule), fp16 operands
// A fragment layout (mma.m16n8k16 A): [m16_blk(256)][k16(256)][lane(32)][a0..a3] (16B/lane)
__device__ __half g_act[(size_t)MPAD * DD];
// B pair-packed layout: [n8_blk(4000)][ksp(128)][lane(32)][b0e,b1e,b0o,b1o] (16B/lane)
__device__ __half g_w[(size_t)VV * DD];

// ============================ helpers ============================
__device__ __forceinline__ uint32_t smem_u32(const void* p) {
    uint32_t a;
    asm("{ .reg .u64 t; cvta.to.shared.u64 t, %1; cvt.u32.u64 %0, t; }" : "=r"(a) : "l"(p));
    return a;
}
__device__ __forceinline__ void cp16(uint32_t dst, const void* src) {
    asm volatile("cp.async.cg.shared.global [%0], [%1], 16;" :: "r"(dst), "l"(src));
}
#define CP_COMMIT() asm volatile("cp.async.commit_group;" ::: "memory")
#define CP_WAIT1()  asm volatile("cp.async.wait_group 1;" ::: "memory")

__device__ __forceinline__ void mma_f16(float* d, const uint32_t* a, uint32_t b0, uint32_t b1) {
    asm volatile(
        "mma.sync.aligned.m16n8k16.row.col.f32.f16.f16.f32 "
        "{%0,%1,%2,%3}, {%4,%5,%6,%7}, {%8,%9}, {%0,%1,%2,%3};"
        : "+f"(d[0]), "+f"(d[1]), "+f"(d[2]), "+f"(d[3])
        : "r"(a[0]), "r"(a[1]), "r"(a[2]), "r"(a[3]), "r"(b0), "r"(b1));
}

__device__ __forceinline__ uint32_t packh2(float lo, float hi) {
    __half2 h = __floats2half2_rn(lo, hi);
    return *reinterpret_cast<uint32_t*>(&h);
}

// ============================ prolog kernels ============================
// Permute + fp16-round lm_head_weight [VV, DD] -> g_w pair-packed fragment layout.
// Thread gid = (n8b*128 + ksp)*32 + lane, lane = (n%8)*4 + c. Reads 4 float2 from
// row n = n8b*8 + lane/4; writes one uint4 {b0e,b1e,b0o,b1o}. Warp writes 512B contig.
__global__ void __launch_bounds__(256) wperm_kernel(const float* __restrict__ w,
                                                    uint4* __restrict__ o) {
    int gid = blockIdx.x * 256 + threadIdx.x;      // (VV/8)*128*32 threads
    int lane = gid & 31;
    int ksp  = (gid >> 5) & 127;
    int n8b  = gid >> 12;
    int c = lane & 3;
    int n = n8b * 8 + (lane >> 2);
    const float2* src = reinterpret_cast<const float2*>(w + (size_t)n * DD + ksp * 32 + 2 * c);
    float2 e0 = src[0];    // k = 2c, 2c+1        (even k16, b0)
    float2 e1 = src[4];    // k = 2c+8, 2c+9      (even k16, b1)
    float2 o0 = src[8];    // k = 16+2c, 16+2c+1  (odd k16, b0)
    float2 o1 = src[12];   // k = 24+2c, ...      (odd k16, b1)
    uint4 v;
    v.x = packh2(e0.x, e0.y);
    v.y = packh2(e1.x, e1.y);
    v.z = packh2(o0.x, o0.y);
    v.w = packh2(o1.x, o1.y);
    o[gid] = v;
}

// RMSNorm one (shifted) row per block, fp16-rounded, A fragment layout (unchanged).
__global__ void __launch_bounds__(256) rmsperm_kernel(const float* __restrict__ x,
                                                      const float* __restrict__ w,
                                                      uint32_t* __restrict__ o) {
    __shared__ float red[8];
    int r = blockIdx.x, t = threadIdx.x;
    float vals[16];
    if (r < MROWS) {
        int b = r / (SS - 1);
        int s = r - b * (SS - 1);
        const float4* xr = reinterpret_cast<const float4*>(x + ((size_t)b * SS + s) * DD + t * 16);
        const float4* wr = reinterpret_cast<const float4*>(w + t * 16);
        float4 q[4];
        float acc = 0.f;
#pragma unroll
        for (int i = 0; i < 4; ++i) {
            q[i] = xr[i];
            acc += q[i].x * q[i].x + q[i].y * q[i].y + q[i].z * q[i].z + q[i].w * q[i].w;
        }
#pragma unroll
        for (int off = 16; off; off >>= 1) acc += __shfl_xor_sync(0xffffffffu, acc, off);
        if ((t & 31) == 0) red[t >> 5] = acc;
        __syncthreads();
        float tot = red[0] + red[1] + red[2] + red[3] + red[4] + red[5] + red[6] + red[7];
        float rs = rsqrtf(tot * (1.0f / DD) + 1e-6f);
#pragma unroll
        for (int i = 0; i < 4; ++i) {
            float4 wv = wr[i];
            vals[4 * i + 0] = q[i].x * rs * wv.x;
            vals[4 * i + 1] = q[i].y * rs * wv.y;
            vals[4 * i + 2] = q[i].z * rs * wv.z;
            vals[4 * i + 3] = q[i].w * rs * wv.w;
        }
    } else {
#pragma unroll
        for (int i = 0; i < 16; ++i) vals[i] = 0.f;
        __syncthreads();   // keep barrier count uniform
    }
    int m16 = r >> 4, ri = r & 15;
    int slotb = ri >> 3;
    size_t laneBase = ((size_t)m16 * 256 + t) * 32 + (ri & 7) * 4;
#pragma unroll
    for (int c = 0; c < 4; ++c) {
        size_t li = (laneBase + c) * 4;
        o[li + slotb]     = packh2(vals[2 * c],     vals[2 * c + 1]);
        o[li + slotb + 2] = packh2(vals[2 * c + 8], vals[2 * c + 9]);
    }
}

// Shifted labels -> float32 tail of d_out (layout proven in R3/R4).
__global__ void __launch_bounds__(256) labels_kernel(const int* __restrict__ lab,
                                                     float* __restrict__ out, long long rem) {
    int i = blockIdx.x * blockDim.x + threadIdx.x;
    if (i >= MROWS) return;
    int b = i / (SS - 1);
    int s = i - b * (SS - 1);
    int v = lab[(size_t)b * SS + s + 1];
    size_t base = (size_t)MROWS * VV;
    if (rem >= 2LL * MROWS) {
        reinterpret_cast<long long*>(out + base)[i] = (long long)v;
    } else if (rem >= (long long)MROWS) {
        out[base + i] = (float)v;
    }
}

// ============================ GEMM kernel ============================
// CTA 128x128, kBlock 64 (2 ks-pairs), 3-stage cp.async pipeline, ONE barrier/iter.
// 8 warps (4m x 2n), warp tile 32x64, 64 fp32 accums/thread.
#define NSTG      3
#define STG_BYTES 32768                 // A 16KB + B 16KB per stage
#define KBLOCKS   (DD / 64)             // 64

__global__ void __launch_bounds__(256, 2) gemm_kernel(const __half* __restrict__ A,
                                                      const __half* __restrict__ B,
                                                      float* __restrict__ out) {
    extern __shared__ char smem[];
    uint32_t sbase = smem_u32(smem);
    int t = threadIdx.x;
    int lane = t & 31, wid = t >> 5;
    int wm = wid & 3, wn = wid >> 2;
    int m_tile = blockIdx.x & 31;       // m fastest: A (32MB fp16) L2-resident
    int n_tile = blockIdx.x >> 5;

    const char* Ab = (const char*)A;
    const char* Bb = (const char*)B;

    // stage fill: pure 16B cp.async copies (gmem fragment layout == smem layout)
    auto load_stage = [&](int st, int kb) {
        uint32_t dstA = sbase + st * STG_BYTES;
        uint32_t dstB = dstA + 16384;
#pragma unroll
        for (int pp = 0; pp < 4; ++pp) {            // A: 1024 x 16B chunks
            int q = pp * 256 + t;                   // q = (m16b*4 + ks)*32 + ln
            int ln = q & 31, ks = (q >> 5) & 3, m16b = q >> 7;
            const char* src = Ab + ((((size_t)(m_tile * 8 + m16b) * 256 + kb * 4 + ks) * 32 + ln) << 4);
            cp16(dstA + (q << 4), src);
        }
#pragma unroll
        for (int pp = 0; pp < 4; ++pp) {            // B: 1024 x 16B chunks
            int q = pp * 256 + t;                   // q = (n8b*2 + kspl)*32 + ln
            int ln = q & 31, kspl = (q >> 5) & 1, n8b = q >> 6;
            const char* src = Bb + ((((size_t)(n_tile * 16 + n8b) * 128 + kb * 2 + kspl) * 32 + ln) << 4);
            cp16(dstB + (q << 4), src);
        }
    };

    float acc[2][8][4];
#pragma unroll
    for (int i = 0; i < 2; ++i)
#pragma unroll
        for (int j = 0; j < 8; ++j)
#pragma unroll
            for (int c = 0; c < 4; ++c) acc[i][j][c] = 0.f;

    // prologue: fill 3 stages (3 commit groups)
#pragma unroll
    for (int s = 0; s < NSTG; ++s) {
        load_stage(s, s);
        CP_COMMIT();
    }

    int st = 0;
    for (int kb = 0; kb < KBLOCKS; ++kb) {
        CP_WAIT1();                     // all but newest group done -> stage kb ready
        __syncthreads();                // single barrier: slot (kb-1)%NSTG now free
        if (kb >= 1) {
            if (kb + 2 < KBLOCKS) load_stage((kb + 2) % NSTG, kb + 2);
            CP_COMMIT();                // commit every iter (possibly empty group)
        }

        const uint4* Asp = reinterpret_cast<const uint4*>(smem + st * STG_BYTES);
        const uint4* Bsp = reinterpret_cast<const uint4*>(smem + st * STG_BYTES + 16384);
#pragma unroll
        for (int kspl = 0; kspl < 2; ++kspl) {
            uint4 bf[8];                               // 8 lds.128: B for BOTH ks halves
#pragma unroll
            for (int j = 0; j < 8; ++j)
                bf[j] = Bsp[(((wn * 8 + j) * 2 + kspl) * 32) + lane];
#pragma unroll
            for (int ks2 = 0; ks2 < 2; ++ks2) {
                int ks = kspl * 2 + ks2;
                uint4 a[2];                            // 2 lds.128
#pragma unroll
                for (int i = 0; i < 2; ++i)
                    a[i] = Asp[(((wm * 2 + i) * 4 + ks) * 32) + lane];
#pragma unroll
                for (int i = 0; i < 2; ++i)
#pragma unroll
                    for (int j = 0; j < 8; ++j) {
                        uint32_t b0 = ks2 ? bf[j].z : bf[j].x;
                        uint32_t b1 = ks2 ? bf[j].w : bf[j].y;
                        mma_f16(acc[i][j], (const uint32_t*)&a[i], b0, b1);
                    }
            }
        }
        st = (st == NSTG - 1) ? 0 : st + 1;
    }

    // epilogue: fragment layout -> row-major fp32 logits
    int gq = lane >> 2, tq = lane & 3;
#pragma unroll
    for (int i = 0; i < 2; ++i) {
        int r0 = m_tile * 128 + wm * 32 + i * 16 + gq;
#pragma unroll
        for (int j = 0; j < 8; ++j) {
            int col = n_tile * 128 + wn * 64 + j * 8 + tq * 2;
            if (r0 < MROWS)
                *reinterpret_cast<float2*>(out + (size_t)r0 * VV + col) =
                    make_float2(acc[i][j][0], acc[i][j][1]);
            if (r0 + 8 < MROWS)
                *reinterpret_cast<float2*>(out + (size_t)(r0 + 8) * VV + col) =
                    make_float2(acc[i][j][2], acc[i][j][3]);
        }
    }
}

// ============================ host launcher ============================
extern "C" void kernel_launch(void* const* d_in, const int* in_sizes, int n_in,
                              void* d_out, int out_size) {
    const float* hs  = (const float*)d_in[0];
    const float* nw  = (const float*)d_in[1];
    const float* lmw = (const float*)d_in[2];
    const int*   lab = (const int*)d_in[4];
    float* out = (float*)d_out;

    void* act_ptr = nullptr; cudaGetSymbolAddress(&act_ptr, g_act);
    void* w_ptr   = nullptr; cudaGetSymbolAddress(&w_ptr, g_w);

    // prolog: permute/round weights + rmsnorm activations + labels
    wperm_kernel<<<(VV / 8) * 128 * 32 / 256, 256>>>(lmw, (uint4*)w_ptr);
    rmsperm_kernel<<<MPAD, 256>>>(hs, nw, (uint32_t*)act_ptr);
    long long rem = (long long)out_size - (long long)MROWS * VV;
    labels_kernel<<<(MROWS + 255) / 256, 256>>>(lab, out, rem);

    // GEMM: 32 m-tiles x 250 n-tiles
    cudaFuncSetAttribute(gemm_kernel, cudaFuncAttributeMaxDynamicSharedMemorySize,
                         NSTG * STG_BYTES);
    gemm_kernel<<<32 * 250, 256, NSTG * STG_BYTES>>>((const __half*)act_ptr,
                                                     (const __half*)w_ptr, out);
}